// round 14
// baseline (speedup 1.0000x reference)
#include <cuda_runtime.h>
#include <cuda_bf16.h>
#include <math.h>
#include <stdint.h>

#define C_     128
#define BATCH  2
#define S_     110592          // 48*48*48
#define NPTS   221184
#define CH     512
#define NPANEL 1728            // NPTS/128
#define PPB    864             // panels per batch

typedef unsigned int uint;
typedef unsigned short ushort;

extern __shared__ __align__(128) unsigned char smraw[];

// ---------------- scratch ----------------
__device__ float  g_yconv[(size_t)BATCH * C_ * S_];
__device__ ushort g_ylnh[(size_t)NPTS * C_];            // LN out hi bf16, [panel][m][k]
__device__ ushort g_ylnl[(size_t)NPTS * C_];
__device__ ushort g_hh  [(size_t)NPTS * CH];            // gelu out hi, [panel][m][e]
__device__ ushort g_hl  [(size_t)NPTS * CH];
__device__ ushort g_w1h [CH * C_];                      // w1^T hi: [e][c]
__device__ ushort g_w1l [CH * C_];
__device__ ushort g_w2h [BATCH * C_ * CH];              // scaled w2^T hi: [b][c][e]
__device__ ushort g_w2l [BATCH * C_ * CH];
__device__ float  g_gsq [BATCH * CH];
__device__ float  g_s   [BATCH * CH];
__device__ float  g_bias2[C_];

// ---------------- PTX helpers ----------------
__device__ __forceinline__ uint32_t smem_u32(const void* p) {
    uint32_t a;
    asm("{ .reg .u64 t; cvta.to.shared.u64 t, %1; cvt.u32.u64 %0, t; }" : "=r"(a) : "l"(p));
    return a;
}
#define CP_ASYNC(dst, src) asm volatile("cp.async.cg.shared.global [%0], [%1], 16;" :: "r"(dst), "l"(src))
#define CP_COMMIT()        asm volatile("cp.async.commit_group;")
#define CP_WAIT1()         asm volatile("cp.async.wait_group 1;")
#define CP_WAIT0()         asm volatile("cp.async.wait_group 0;")

__device__ __forceinline__ void ldsm4(uint* r, uint32_t addr) {
    asm volatile("ldmatrix.sync.aligned.m8n8.x4.shared.b16 {%0,%1,%2,%3}, [%4];"
        : "=r"(r[0]), "=r"(r[1]), "=r"(r[2]), "=r"(r[3]) : "r"(addr));
}
__device__ __forceinline__ void mma_bf16(float* c, const uint* a, uint b0, uint b1) {
    asm volatile("mma.sync.aligned.m16n8k16.row.col.f32.bf16.bf16.f32 "
        "{%0,%1,%2,%3}, {%4,%5,%6,%7}, {%8,%9}, {%0,%1,%2,%3};"
        : "+f"(c[0]), "+f"(c[1]), "+f"(c[2]), "+f"(c[3])
        : "r"(a[0]), "r"(a[1]), "r"(a[2]), "r"(a[3]), "r"(b0), "r"(b1));
}
__device__ __forceinline__ void split2(float a, float b, uint& hi, uint& lo) {
    __nv_bfloat16 ah = __float2bfloat16_rn(a), bh = __float2bfloat16_rn(b);
    float ar = a - __bfloat162float(ah), br = b - __bfloat162float(bh);
    __nv_bfloat16 al = __float2bfloat16_rn(ar), bl = __float2bfloat16_rn(br);
    hi = ((uint)__bfloat16_as_ushort(bh) << 16) | (uint)__bfloat16_as_ushort(ah);
    lo = ((uint)__bfloat16_as_ushort(bl) << 16) | (uint)__bfloat16_as_ushort(al);
}
__device__ __forceinline__ float gelu_f(float v) {
    return 0.5f * v * (1.0f + erff(v * 0.70710678118654752f));
}

// generic 16-k sub-stage compute; plane offsets are template constants.
template<int ALO, int BBASE, int BLO>
__device__ __forceinline__ void gemm_compute_sub(uint32_t sa,
    int ar, int asw, int br, int bsw, float acc[4][4][4]) {
    uint aH[4][4], aL[4][4], bH[2][4], bL[2][4];
    uint32_t abase = sa + (uint32_t)(ar * 32 + asw * 16);
    #pragma unroll
    for (int i = 0; i < 4; ++i) ldsm4(aH[i], abase + i * 512u);
    #pragma unroll
    for (int i = 0; i < 4; ++i) ldsm4(aL[i], abase + (uint32_t)ALO + i * 512u);
    uint32_t bbase = sa + (uint32_t)BBASE + (uint32_t)(br * 32 + bsw * 16);
    #pragma unroll
    for (int j = 0; j < 2; ++j) ldsm4(bH[j], bbase + j * 512u);
    #pragma unroll
    for (int j = 0; j < 2; ++j) ldsm4(bL[j], bbase + (uint32_t)BLO + j * 512u);
    #pragma unroll
    for (int i = 0; i < 4; ++i)
        #pragma unroll
        for (int j = 0; j < 4; ++j) {
            uint h0 = bH[j >> 1][(j & 1) * 2], h1 = bH[j >> 1][(j & 1) * 2 + 1];
            uint l0 = bL[j >> 1][(j & 1) * 2], l1 = bL[j >> 1][(j & 1) * 2 + 1];
            mma_bf16(acc[i][j], aH[i], h0, h1);
            mma_bf16(acc[i][j], aH[i], l0, l1);
            mma_bf16(acc[i][j], aL[i], h0, h1);
        }
}

// ---------------- K0: w1 cvt + zero gsq ----------------
__global__ void w1cvt_zero_kernel(const float* __restrict__ w1) {
    if (blockIdx.x == 128) {
        int i = threadIdx.x;
        if (i < BATCH * CH) g_gsq[i] = 0.f;
        return;
    }
    int id = blockIdx.x * 512 + threadIdx.x;
    int cc = id >> 9, e = id & 511;
    float v = w1[id];
    __nv_bfloat16 h = __float2bfloat16_rn(v);
    float rem = v - __bfloat162float(h);
    g_w1h[e * 128 + cc] = __bfloat16_as_ushort(h);
    g_w1l[e * 128 + cc] = __bfloat16_as_ushort(__float2bfloat16_rn(rem));
}

// ---------------- K1: depthwise 7x7x7 conv (plain FFMA, known-best) ----------------
__global__ void conv_dw_kernel(const float* __restrict__ x, const float* __restrict__ dw_w) {
    float* sm = (float*)smraw;
    float* planes = sm;
    float* wsm    = sm + 7 * 2916;
    float* outsm  = wsm + 343;

    const int tid = threadIdx.x;
    const int dstart = blockIdx.x * 12;
    const int c = blockIdx.y;
    const int b = blockIdx.z;
    const size_t xbase = ((size_t)(b * C_ + c)) * S_;

    for (int i = tid; i < 343; i += 192) wsm[i] = dw_w[c * 343 + i];

    for (int pl = 0; pl < 7; ++pl) {
        int din = dstart - 3 + pl;
        int slot = ((din % 7) + 7) % 7;
        float* dst = planes + slot * 2916;
        if (din < 0 || din >= 48) {
            for (int i = tid; i < 2916; i += 192) dst[i] = 0.f;
        } else {
            const float* src = x + xbase + (size_t)din * 2304;
            for (int i = tid; i < 2916; i += 192) {
                int hh = i / 54 - 3, ww = i % 54 - 3;
                dst[i] = (hh >= 0 && hh < 48 && ww >= 0 && ww < 48) ? src[hh * 48 + ww] : 0.f;
            }
        }
    }

    const int tx = tid & 7, ty = tid >> 3;
    const int w0 = tx * 6, h0 = ty * 2;

    for (int d = dstart; d < dstart + 12; ++d) {
        __syncthreads();
        float acc[2][6];
        #pragma unroll
        for (int r = 0; r < 2; ++r)
            #pragma unroll
            for (int j = 0; j < 6; ++j) acc[r][j] = 0.f;

        #pragma unroll 1
        for (int dd = 0; dd < 7; ++dd) {
            const float* pl = planes + (((d - 3 + dd) % 7 + 7) % 7) * 2916;
            #pragma unroll
            for (int dh = 0; dh < 7; ++dh) {
                float wv[7];
                #pragma unroll
                for (int k = 0; k < 7; ++k) wv[k] = wsm[dd * 49 + dh * 7 + k];
                #pragma unroll
                for (int r = 0; r < 2; ++r) {
                    const float* row = pl + (h0 + r + dh) * 54 + w0;
                    float xr[12];
                    #pragma unroll
                    for (int q = 0; q < 12; ++q) xr[q] = row[q];
                    #pragma unroll
                    for (int j = 0; j < 6; ++j)
                        #pragma unroll
                        for (int k = 0; k < 7; ++k)
                            acc[r][j] = fmaf(xr[j + k], wv[k], acc[r][j]);
                }
            }
        }
        #pragma unroll
        for (int r = 0; r < 2; ++r)
            #pragma unroll
            for (int j = 0; j < 6; ++j)
                outsm[(h0 + r) * 48 + w0 + j] = acc[r][j];
        __syncthreads();
        float* dst = g_yconv + xbase + (size_t)d * 2304;
        for (int i = tid; i < 2304; i += 192) dst[i] = outsm[i];
        if (d + 1 < dstart + 12) {
            int din = d + 4;
            int slot = ((din % 7) + 7) % 7;
            float* dstp = planes + slot * 2916;
            if (din >= 48) {
                for (int i = tid; i < 2916; i += 192) dstp[i] = 0.f;
            } else {
                const float* src = x + xbase + (size_t)din * 2304;
                for (int i = tid; i < 2916; i += 192) {
                    int hh = i / 54 - 3, ww = i % 54 - 3;
                    dstp[i] = (hh >= 0 && hh < 48 && ww >= 0 && ww < 48) ? src[hh * 48 + ww] : 0.f;
                }
            }
        }
    }
}

// ---------------- K2: transpose + dw_b + LN -> split bf16 [panel][m][k] ----------------
__global__ void trans_ln_kernel(const float* __restrict__ dwb,
                                const float* __restrict__ lng,
                                const float* __restrict__ lnb) {
    __shared__ float tile[C_ * 33];
    __shared__ float ps[256], pq[256], musm[32], rssm[32];
    const int tid = threadIdx.x;
    const int tx = tid & 31, ty = tid >> 5;
    const int p0 = blockIdx.x * 32;
    const int b = blockIdx.y;

    for (int g = 0; g < 16; ++g) {
        int c = ty * 16 + g;
        tile[c * 33 + tx] = g_yconv[((size_t)(b * C_ + c)) * S_ + p0 + tx] + dwb[c];
    }
    __syncthreads();
    float s = 0.f, q = 0.f;
    for (int g = 0; g < 16; ++g) {
        float v = tile[(ty * 16 + g) * 33 + tx];
        s += v; q += v * v;
    }
    ps[ty * 32 + tx] = s; pq[ty * 32 + tx] = q;
    __syncthreads();
    if (ty == 0) {
        float S1 = 0.f, Q1 = 0.f;
        for (int u = 0; u < 8; ++u) { S1 += ps[u * 32 + tx]; Q1 += pq[u * 32 + tx]; }
        float mu = S1 * (1.f / 128.f);
        float var = Q1 * (1.f / 128.f) - mu * mu;
        musm[tx] = mu;
        rssm[tx] = rsqrtf(var + 1e-6f);
    }
    __syncthreads();
    size_t panel = ((size_t)b * S_ + p0) >> 7;
    int mo = (int)(((size_t)b * S_ + p0) & 127);
    ushort* dh = g_ylnh + panel * 16384;
    ushort* dl = g_ylnl + panel * 16384;
    for (int t = 0; t < 16; ++t) {
        int idx = tid + 256 * t;
        int c = idx & 127, pp = idx >> 7;
        float v = (tile[c * 33 + pp] - musm[pp]) * rssm[pp] * lng[c] + lnb[c];
        __nv_bfloat16 h = __float2bfloat16_rn(v);
        float rem = v - __bfloat162float(h);
        dh[(mo + pp) * 128 + c] = __bfloat16_as_ushort(h);
        dl[(mo + pp) * 128 + c] = __bfloat16_as_ushort(__float2bfloat16_rn(rem));
    }
}

// ---------------- K3: GEMM1 tile 128x128, 256 threads, 3-stage ring, staged epilogue ----------------
// mainloop: 3 buffers of 32KB @0/32768/65536; epilogue: hi plane @0 (272B rows), lo @34816
#define G1_SMEM 98304
__global__ void __launch_bounds__(256, 2) gemm1_mma(const float* __restrict__ b1) {
    const int tid = threadIdx.x;
    const int n0 = blockIdx.x * 128;
    const int bx = blockIdx.y;
    const uint32_t smb = smem_u32(smraw);

    const int r = tid >> 1, cc = tid & 1;
    const int csw = (cc ^ ((r >> 2) & 1)) & 1;
    const uint32_t sdst0 = smb + (uint32_t)(r * 32 + csw * 16);
    const char* gAh = (const char*)(g_ylnh + (size_t)bx * 16384 + r * 128 + cc * 8);
    const char* gAl = (const char*)(g_ylnl + (size_t)bx * 16384 + r * 128 + cc * 8);
    const char* gBh = (const char*)(g_w1h + (size_t)(n0 + r) * 128 + cc * 8);
    const char* gBl = (const char*)(g_w1l + (size_t)(n0 + r) * 128 + cc * 8);

    const int L = tid & 31, wid = tid >> 5, wm = wid & 1, wn = wid >> 1;
    const int ar = wm * 64 + ((L & 7) | (((L >> 3) & 1) << 3));
    const int asw = (((L >> 4) & 1) ^ ((ar >> 2) & 1)) & 1;
    const int br = wn * 32 + ((L & 7) | (((L >> 4) & 1) << 3));
    const int bsw = (((L >> 3) & 1) ^ ((br >> 2) & 1)) & 1;

    float acc[4][4][4];
    #pragma unroll
    for (int i = 0; i < 4; ++i)
        #pragma unroll
        for (int j = 0; j < 4; ++j)
            #pragma unroll
            for (int k = 0; k < 4; ++k) acc[i][j][k] = 0.f;

    auto load_macro = [&](uint32_t bufoff, int ms) {
        #pragma unroll
        for (int s = 0; s < 2; ++s) {
            int ks = 2 * ms + s;
            uint32_t so = bufoff + (uint32_t)s * 16384u;
            CP_ASYNC(sdst0 + so,           gAh + ks * 32);
            CP_ASYNC(sdst0 + so + 4096u,   gAl + ks * 32);
            CP_ASYNC(sdst0 + so + 8192u,   gBh + ks * 32);
            CP_ASYNC(sdst0 + so + 12288u,  gBl + ks * 32);
        }
        CP_COMMIT();
    };
    auto compute_macro = [&](uint32_t bufoff) {
        gemm_compute_sub<4096, 8192, 4096>(smb + bufoff,          ar, asw, br, bsw, acc);
        gemm_compute_sub<4096, 8192, 4096>(smb + bufoff + 16384u, ar, asw, br, bsw, acc);
    };

    // fully unrolled 4-macro schedule on 3 buffers (0,32K,64K), 1 sync per macro
    load_macro(0u, 0);
    load_macro(32768u, 1);
    CP_WAIT1(); __syncthreads();
    load_macro(65536u, 2);
    compute_macro(0u);
    CP_WAIT1(); __syncthreads();
    load_macro(0u, 3);
    compute_macro(32768u);
    CP_WAIT1(); __syncthreads();
    compute_macro(65536u);
    CP_WAIT0(); __syncthreads();
    compute_macro(0u);

    // epilogue: gelu + split -> staged smem planes (272B rows, 16B-aligned) -> coalesced stores
    __syncthreads();                      // mainloop smem reads done before overlay writes
    const int bloc = (bx >= PPB) ? 1 : 0;
    uint* smHI = (uint*)smraw;            // [128 rows][68 uints]
    uint* smLO = (uint*)(smraw + 34816);
    float sqa[4][2];
    #pragma unroll
    for (int j = 0; j < 4; ++j) { sqa[j][0] = 0.f; sqa[j][1] = 0.f; }

    #pragma unroll
    for (int i = 0; i < 4; ++i) {
        const int m = wm * 64 + i * 16 + (L >> 2);
        #pragma unroll
        for (int j = 0; j < 4; ++j) {
            const int nl = wn * 32 + j * 8 + (L & 3) * 2;
            float b10 = __ldg(b1 + n0 + nl), b11 = __ldg(b1 + n0 + nl + 1);
            float v00 = gelu_f(acc[i][j][0] + b10);
            float v01 = gelu_f(acc[i][j][1] + b11);
            float v10 = gelu_f(acc[i][j][2] + b10);
            float v11 = gelu_f(acc[i][j][3] + b11);
            sqa[j][0] += v00 * v00 + v10 * v10;
            sqa[j][1] += v01 * v01 + v11 * v11;
            uint hi0, lo0, hi1, lo1;
            split2(v00, v01, hi0, lo0);
            split2(v10, v11, hi1, lo1);
            smHI[m * 68 + (nl >> 1)]       = hi0;
            smLO[m * 68 + (nl >> 1)]       = lo0;
            smHI[(m + 8) * 68 + (nl >> 1)] = hi1;
            smLO[(m + 8) * 68 + (nl >> 1)] = lo1;
        }
    }
    #pragma unroll
    for (int j = 0; j < 4; ++j) {
        float s0 = sqa[j][0], s1 = sqa[j][1];
        #pragma unroll
        for (int o = 16; o >= 4; o >>= 1) {
            s0 += __shfl_xor_sync(0xffffffffu, s0, o);
            s1 += __shfl_xor_sync(0xffffffffu, s1, o);
        }
        if (L < 4) {
            int n = n0 + wn * 32 + j * 8 + L * 2;
            atomicAdd(&g_gsq[bloc * CH + n], s0);
            atomicAdd(&g_gsq[bloc * CH + n + 1], s1);
        }
    }
    __syncthreads();
    #pragma unroll
    for (int t = 0; t < 16; ++t) {
        int idx = t * 256 + tid;               // 0..4095 uint4s
        int plane = idx >> 11;                 // 2048 uint4 per plane
        int rem = idx & 2047;
        int row = rem >> 4, c4 = rem & 15;     // 16 uint4 per row
        uint4 v = *(const uint4*)(smraw + (uint32_t)plane * 34816u + row * 272 + c4 * 16);
        ushort* base = (plane ? g_hl : g_hh) + (size_t)bx * 65536 + (size_t)row * 512 + n0;
        *(uint4*)((char*)base + c4 * 16) = v;
    }
}

// ---------------- K4: GRN scale + bias2 ----------------
__global__ void grn_prep_kernel(const float* __restrict__ grn_g, const float* __restrict__ grn_b,
                                const float* __restrict__ w2, const float* __restrict__ b2) {
    if (blockIdx.x == 0) {
        __shared__ float red[512];
        int e = threadIdx.x;
        for (int b = 0; b < BATCH; ++b) {
            float g = sqrtf(g_gsq[b * CH + e]);
            red[e] = g;
            __syncthreads();
            for (int o = 256; o > 0; o >>= 1) {
                if (e < o) red[e] += red[e + o];
                __syncthreads();
            }
            float mean = red[0] * (1.f / 512.f);
            __syncthreads();
            float nx = g / (mean + 1e-6f);
            g_s[b * CH + e] = 1.f + grn_g[e] * nx;
        }
    } else {
        int c = threadIdx.x;
        if (c < C_) {
            float a = b2[c];
            for (int e = 0; e < CH; ++e) a += grn_b[e] * w2[e * C_ + c];
            g_bias2[c] = a;
        }
    }
}

// ---------------- K4b: scaled w2 -> transposed split bf16 planes [b][c][e] ----------------
__global__ void w2cvt_kernel(const float* __restrict__ w2) {
    int id = blockIdx.x * 512 + threadIdx.x;
    int e = id >> 7, c = id & 127;
    float w = w2[id];
    #pragma unroll
    for (int b = 0; b < BATCH; ++b) {
        float v = g_s[b * CH + e] * w;
        __nv_bfloat16 h = __float2bfloat16_rn(v);
        float rem = v - __bfloat162float(h);
        g_w2h[(size_t)b * 65536 + c * 512 + e] = __bfloat16_as_ushort(h);
        g_w2l[(size_t)b * 65536 + c * 512 + e] = __bfloat16_as_ushort(__float2bfloat16_rn(rem));
    }
}

// ---------------- K5: GEMM2 tile 256x128, 512 threads, 3-stage ring ----------------
// 3 buffers of 48KB @0/49152/98304; epilogue C stage 256x129 f32 = 132096
#define G2_SMEM 147456
#define PPB2    432
__global__ void __launch_bounds__(512, 1) gemm2_mma(const float* __restrict__ xin,
                                                    float* __restrict__ out) {
    const int tid = threadIdx.x;
    const int bx = blockIdx.x;
    const int bloc = (bx >= PPB2) ? 1 : 0;
    const uint32_t smb = smem_u32(smraw);

    const int ra = tid >> 1, ca = tid & 1;
    const ushort* gAh = g_hh + (size_t)bx * 131072 + (size_t)ra * 512 + ca * 8;
    const ushort* gAl = g_hl + (size_t)bx * 131072 + (size_t)ra * 512 + ca * 8;
    const uint32_t dAc = (uint32_t)(ra * 32 + ((ca ^ ((ra >> 2) & 1)) * 16));
    const int rb = (tid & 255) >> 1, cb = tid & 1;
    const ushort* gB = (tid < 256 ? g_w2h : g_w2l) + (size_t)bloc * 65536 + (size_t)rb * 512 + cb * 8;
    const uint32_t dBc = (uint32_t)(16384 + (tid < 256 ? 0 : 4096) + rb * 32 + ((cb ^ ((rb >> 2) & 1)) * 16));

    const int L = tid & 31, wid = tid >> 5, wm = wid & 3, wn = wid >> 2;
    const int ar = wm * 64 + ((L & 7) | (((L >> 3) & 1) << 3));
    const int asw = (((L >> 4) & 1) ^ ((ar >> 2) & 1)) & 1;
    const int br = wn * 32 + ((L & 7) | (((L >> 4) & 1) << 3));
    const int bsw = (((L >> 3) & 1) ^ ((br >> 2) & 1)) & 1;

    float acc[4][4][4];
    #pragma unroll
    for (int i = 0; i < 4; ++i)
        #pragma unroll
        for (int j = 0; j < 4; ++j)
            #pragma unroll
            for (int k = 0; k < 4; ++k) acc[i][j][k] = 0.f;

    auto load_macro = [&](uint32_t bufoff, int ms) {
        #pragma unroll
        for (int s = 0; s < 2; ++s) {
            int ks = 2 * ms + s;
            uint32_t so = bufoff + (uint32_t)s * 24576u;
            CP_ASYNC(smb + so + dAc,          (const char*)(gAh + ks * 16));
            CP_ASYNC(smb + so + dAc + 8192u,  (const char*)(gAl + ks * 16));
            CP_ASYNC(smb + so + dBc,          (const char*)(gB  + ks * 16));
        }
        CP_COMMIT();
    };

    const int NM = 16;
    uint32_t bc = 0u, bn = 49152u, bl = 98304u;   // compute / next / load-target
    load_macro(0u, 0);
    load_macro(49152u, 1);
    for (int ms = 0; ms < NM; ++ms) {
        if (ms == NM - 1) CP_WAIT0(); else CP_WAIT1();
        __syncthreads();
        if (ms + 2 < NM) load_macro(bl, ms + 2);
        gemm_compute_sub<8192, 16384, 4096>(smb + bc,          ar, asw, br, bsw, acc);
        gemm_compute_sub<8192, 16384, 4096>(smb + bc + 24576u, ar, asw, br, bsw, acc);
        uint32_t t = bc; bc = bn; bn = bl; bl = t;
    }

    // epilogue: stage C[m 256][c 129], then coalesced NCDHW write with residual
    __syncthreads();
    float* Cs = (float*)smraw;
    #pragma unroll
    for (int i = 0; i < 4; ++i) {
        const int m = wm * 64 + i * 16 + (L >> 2);
        #pragma unroll
        for (int j = 0; j < 4; ++j) {
            const int c = wn * 32 + j * 8 + (L & 3) * 2;
            float bv0 = g_bias2[c], bv1 = g_bias2[c + 1];
            Cs[m * 129 + c]           = acc[i][j][0] + bv0;
            Cs[m * 129 + c + 1]       = acc[i][j][1] + bv1;
            Cs[(m + 8) * 129 + c]     = acc[i][j][2] + bv0;
            Cs[(m + 8) * 129 + c + 1] = acc[i][j][3] + bv1;
        }
    }
    __syncthreads();
    const int p0 = (bx - bloc * PPB2) * 256;
    #pragma unroll
    for (int t = 0; t < 64; ++t) {
        int idx = tid + 512 * t;
        int p = idx & 255, c = idx >> 8;
        size_t gi = ((size_t)(bloc * C_ + c)) * S_ + p0 + p;
        out[gi] = xin[gi] + Cs[p * 129 + c];
    }
}

// ---------------- launch ----------------
extern "C" void kernel_launch(void* const* d_in, const int* in_sizes, int n_in,
                              void* d_out, int out_size) {
    (void)in_sizes; (void)n_in; (void)out_size;
    const float* x     = (const float*)d_in[0];
    const float* dw_w  = (const float*)d_in[1];
    const float* dw_b  = (const float*)d_in[2];
    const float* ln_g  = (const float*)d_in[3];
    const float* ln_b  = (const float*)d_in[4];
    const float* w1    = (const float*)d_in[5];
    const float* b1    = (const float*)d_in[6];
    const float* grn_g = (const float*)d_in[7];
    const float* grn_b = (const float*)d_in[8];
    const float* w2    = (const float*)d_in[9];
    const float* b2    = (const float*)d_in[10];
    float* out = (float*)d_out;

    const int conv_smem = (7 * 2916 + 343 + 2304) * 4;   // 92236
    cudaFuncSetAttribute(conv_dw_kernel, cudaFuncAttributeMaxDynamicSharedMemorySize, conv_smem);
    cudaFuncSetAttribute(gemm1_mma, cudaFuncAttributeMaxDynamicSharedMemorySize, G1_SMEM);
    cudaFuncSetAttribute(gemm2_mma, cudaFuncAttributeMaxDynamicSharedMemorySize, G2_SMEM);

    w1cvt_zero_kernel<<<129, 512>>>(w1);
    conv_dw_kernel<<<dim3(4, C_, BATCH), 192, conv_smem>>>(x, dw_w);
    trans_ln_kernel<<<dim3(S_ / 32, BATCH), 256>>>(dw_b, ln_g, ln_b);
    gemm1_mma<<<dim3(4, NPANEL), 256, G1_SMEM>>>(b1);
    grn_prep_kernel<<<2, 512>>>(grn_g, grn_b, w2, b2);
    w2cvt_kernel<<<128, 512>>>(w2);
    gemm2_mma<<<NPANEL / 2, 512, G2_SMEM>>>(x, out);
}

// round 15
// speedup vs baseline: 1.0110x; 1.0110x over previous
#include <cuda_runtime.h>
#include <cuda_bf16.h>
#include <math.h>
#include <stdint.h>

#define C_     128
#define BATCH  2
#define S_     110592          // 48*48*48
#define NPTS   221184
#define CH     512
#define NPANEL 1728            // NPTS/128
#define PPB    864             // panels per batch

typedef unsigned int uint;
typedef unsigned short ushort;

extern __shared__ __align__(128) unsigned char smraw[];

// ---------------- scratch ----------------
__device__ float  g_yconv[(size_t)BATCH * C_ * S_];
__device__ ushort g_ylnh[(size_t)NPTS * C_];            // LN out hi bf16, [panel][m][k]
__device__ ushort g_ylnl[(size_t)NPTS * C_];
__device__ ushort g_hh  [(size_t)NPTS * CH];            // gelu out hi, [panel][m][e]
__device__ ushort g_hl  [(size_t)NPTS * CH];
__device__ ushort g_w1h [CH * C_];                      // w1^T hi: [e][c]
__device__ ushort g_w1l [CH * C_];
__device__ ushort g_w2h [BATCH * C_ * CH];              // scaled w2^T hi: [b][c][e]
__device__ ushort g_w2l [BATCH * C_ * CH];
__device__ float  g_gsq [BATCH * CH];
__device__ float  g_s   [BATCH * CH];
__device__ float  g_bias2[C_];

// ---------------- PTX helpers ----------------
__device__ __forceinline__ uint32_t smem_u32(const void* p) {
    uint32_t a;
    asm("{ .reg .u64 t; cvta.to.shared.u64 t, %1; cvt.u32.u64 %0, t; }" : "=r"(a) : "l"(p));
    return a;
}
#define CP_ASYNC(dst, src) asm volatile("cp.async.cg.shared.global [%0], [%1], 16;" :: "r"(dst), "l"(src))
#define CP_COMMIT()        asm volatile("cp.async.commit_group;")
#define CP_WAIT1()         asm volatile("cp.async.wait_group 1;")
#define CP_WAIT0()         asm volatile("cp.async.wait_group 0;")

__device__ __forceinline__ void ldsm4(uint* r, uint32_t addr) {
    asm volatile("ldmatrix.sync.aligned.m8n8.x4.shared.b16 {%0,%1,%2,%3}, [%4];"
        : "=r"(r[0]), "=r"(r[1]), "=r"(r[2]), "=r"(r[3]) : "r"(addr));
}
__device__ __forceinline__ void mma_bf16(float* c, const uint* a, uint b0, uint b1) {
    asm volatile("mma.sync.aligned.m16n8k16.row.col.f32.bf16.bf16.f32 "
        "{%0,%1,%2,%3}, {%4,%5,%6,%7}, {%8,%9}, {%0,%1,%2,%3};"
        : "+f"(c[0]), "+f"(c[1]), "+f"(c[2]), "+f"(c[3])
        : "r"(a[0]), "r"(a[1]), "r"(a[2]), "r"(a[3]), "r"(b0), "r"(b1));
}
__device__ __forceinline__ void split2(float a, float b, uint& hi, uint& lo) {
    __nv_bfloat16 ah = __float2bfloat16_rn(a), bh = __float2bfloat16_rn(b);
    float ar = a - __bfloat162float(ah), br = b - __bfloat162float(bh);
    __nv_bfloat16 al = __float2bfloat16_rn(ar), bl = __float2bfloat16_rn(br);
    hi = ((uint)__bfloat16_as_ushort(bh) << 16) | (uint)__bfloat16_as_ushort(ah);
    lo = ((uint)__bfloat16_as_ushort(bl) << 16) | (uint)__bfloat16_as_ushort(al);
}
__device__ __forceinline__ float gelu_f(float v) {
    return 0.5f * v * (1.0f + erff(v * 0.70710678118654752f));
}

// generic 16-k sub-stage compute; NI = number of 16-row A tiles per warp.
template<int NI, int ALO, int BBASE, int BLO>
__device__ __forceinline__ void gemm_compute_subN(uint32_t sa,
    int ar, int asw, int br, int bsw, float acc[][4][4]) {
    uint aH[NI][4], aL[NI][4], bH[2][4], bL[2][4];
    uint32_t abase = sa + (uint32_t)(ar * 32 + asw * 16);
    #pragma unroll
    for (int i = 0; i < NI; ++i) ldsm4(aH[i], abase + i * 512u);
    #pragma unroll
    for (int i = 0; i < NI; ++i) ldsm4(aL[i], abase + (uint32_t)ALO + i * 512u);
    uint32_t bbase = sa + (uint32_t)BBASE + (uint32_t)(br * 32 + bsw * 16);
    #pragma unroll
    for (int j = 0; j < 2; ++j) ldsm4(bH[j], bbase + j * 512u);
    #pragma unroll
    for (int j = 0; j < 2; ++j) ldsm4(bL[j], bbase + (uint32_t)BLO + j * 512u);
    #pragma unroll
    for (int i = 0; i < NI; ++i)
        #pragma unroll
        for (int j = 0; j < 4; ++j) {
            uint h0 = bH[j >> 1][(j & 1) * 2], h1 = bH[j >> 1][(j & 1) * 2 + 1];
            uint l0 = bL[j >> 1][(j & 1) * 2], l1 = bL[j >> 1][(j & 1) * 2 + 1];
            mma_bf16(acc[i][j], aH[i], h0, h1);
            mma_bf16(acc[i][j], aH[i], l0, l1);
            mma_bf16(acc[i][j], aL[i], h0, h1);
        }
}

// ---------------- K0: w1 cvt + zero gsq ----------------
__global__ void w1cvt_zero_kernel(const float* __restrict__ w1) {
    if (blockIdx.x == 128) {
        int i = threadIdx.x;
        if (i < BATCH * CH) g_gsq[i] = 0.f;
        return;
    }
    int id = blockIdx.x * 512 + threadIdx.x;
    int cc = id >> 9, e = id & 511;
    float v = w1[id];
    __nv_bfloat16 h = __float2bfloat16_rn(v);
    float rem = v - __bfloat162float(h);
    g_w1h[e * 128 + cc] = __bfloat16_as_ushort(h);
    g_w1l[e * 128 + cc] = __bfloat16_as_ushort(__float2bfloat16_rn(rem));
}

// ---------------- K1: depthwise 7x7x7 conv (plain FFMA, known-best) ----------------
__global__ void conv_dw_kernel(const float* __restrict__ x, const float* __restrict__ dw_w) {
    float* sm = (float*)smraw;
    float* planes = sm;
    float* wsm    = sm + 7 * 2916;
    float* outsm  = wsm + 343;

    const int tid = threadIdx.x;
    const int dstart = blockIdx.x * 12;
    const int c = blockIdx.y;
    const int b = blockIdx.z;
    const size_t xbase = ((size_t)(b * C_ + c)) * S_;

    for (int i = tid; i < 343; i += 192) wsm[i] = dw_w[c * 343 + i];

    for (int pl = 0; pl < 7; ++pl) {
        int din = dstart - 3 + pl;
        int slot = ((din % 7) + 7) % 7;
        float* dst = planes + slot * 2916;
        if (din < 0 || din >= 48) {
            for (int i = tid; i < 2916; i += 192) dst[i] = 0.f;
        } else {
            const float* src = x + xbase + (size_t)din * 2304;
            for (int i = tid; i < 2916; i += 192) {
                int hh = i / 54 - 3, ww = i % 54 - 3;
                dst[i] = (hh >= 0 && hh < 48 && ww >= 0 && ww < 48) ? src[hh * 48 + ww] : 0.f;
            }
        }
    }

    const int tx = tid & 7, ty = tid >> 3;
    const int w0 = tx * 6, h0 = ty * 2;

    for (int d = dstart; d < dstart + 12; ++d) {
        __syncthreads();
        float acc[2][6];
        #pragma unroll
        for (int r = 0; r < 2; ++r)
            #pragma unroll
            for (int j = 0; j < 6; ++j) acc[r][j] = 0.f;

        #pragma unroll 1
        for (int dd = 0; dd < 7; ++dd) {
            const float* pl = planes + (((d - 3 + dd) % 7 + 7) % 7) * 2916;
            #pragma unroll
            for (int dh = 0; dh < 7; ++dh) {
                float wv[7];
                #pragma unroll
                for (int k = 0; k < 7; ++k) wv[k] = wsm[dd * 49 + dh * 7 + k];
                #pragma unroll
                for (int r = 0; r < 2; ++r) {
                    const float* row = pl + (h0 + r + dh) * 54 + w0;
                    float xr[12];
                    #pragma unroll
                    for (int q = 0; q < 12; ++q) xr[q] = row[q];
                    #pragma unroll
                    for (int j = 0; j < 6; ++j)
                        #pragma unroll
                        for (int k = 0; k < 7; ++k)
                            acc[r][j] = fmaf(xr[j + k], wv[k], acc[r][j]);
                }
            }
        }
        #pragma unroll
        for (int r = 0; r < 2; ++r)
            #pragma unroll
            for (int j = 0; j < 6; ++j)
                outsm[(h0 + r) * 48 + w0 + j] = acc[r][j];
        __syncthreads();
        float* dst = g_yconv + xbase + (size_t)d * 2304;
        for (int i = tid; i < 2304; i += 192) dst[i] = outsm[i];
        if (d + 1 < dstart + 12) {
            int din = d + 4;
            int slot = ((din % 7) + 7) % 7;
            float* dstp = planes + slot * 2916;
            if (din >= 48) {
                for (int i = tid; i < 2916; i += 192) dstp[i] = 0.f;
            } else {
                const float* src = x + xbase + (size_t)din * 2304;
                for (int i = tid; i < 2916; i += 192) {
                    int hh = i / 54 - 3, ww = i % 54 - 3;
                    dstp[i] = (hh >= 0 && hh < 48 && ww >= 0 && ww < 48) ? src[hh * 48 + ww] : 0.f;
                }
            }
        }
    }
}

// ---------------- K2: transpose + dw_b + LN -> split bf16 [panel][m][k] ----------------
__global__ void trans_ln_kernel(const float* __restrict__ dwb,
                                const float* __restrict__ lng,
                                const float* __restrict__ lnb) {
    __shared__ float tile[C_ * 33];
    __shared__ float ps[256], pq[256], musm[32], rssm[32];
    const int tid = threadIdx.x;
    const int tx = tid & 31, ty = tid >> 5;
    const int p0 = blockIdx.x * 32;
    const int b = blockIdx.y;

    for (int g = 0; g < 16; ++g) {
        int c = ty * 16 + g;
        tile[c * 33 + tx] = g_yconv[((size_t)(b * C_ + c)) * S_ + p0 + tx] + dwb[c];
    }
    __syncthreads();
    float s = 0.f, q = 0.f;
    for (int g = 0; g < 16; ++g) {
        float v = tile[(ty * 16 + g) * 33 + tx];
        s += v; q += v * v;
    }
    ps[ty * 32 + tx] = s; pq[ty * 32 + tx] = q;
    __syncthreads();
    if (ty == 0) {
        float S1 = 0.f, Q1 = 0.f;
        for (int u = 0; u < 8; ++u) { S1 += ps[u * 32 + tx]; Q1 += pq[u * 32 + tx]; }
        float mu = S1 * (1.f / 128.f);
        float var = Q1 * (1.f / 128.f) - mu * mu;
        musm[tx] = mu;
        rssm[tx] = rsqrtf(var + 1e-6f);
    }
    __syncthreads();
    size_t panel = ((size_t)b * S_ + p0) >> 7;
    int mo = (int)(((size_t)b * S_ + p0) & 127);
    ushort* dh = g_ylnh + panel * 16384;
    ushort* dl = g_ylnl + panel * 16384;
    for (int t = 0; t < 16; ++t) {
        int idx = tid + 256 * t;
        int c = idx & 127, pp = idx >> 7;
        float v = (tile[c * 33 + pp] - musm[pp]) * rssm[pp] * lng[c] + lnb[c];
        __nv_bfloat16 h = __float2bfloat16_rn(v);
        float rem = v - __bfloat162float(h);
        dh[(mo + pp) * 128 + c] = __bfloat16_as_ushort(h);
        dl[(mo + pp) * 128 + c] = __bfloat16_as_ushort(__float2bfloat16_rn(rem));
    }
}

// ---------------- K3: GEMM1 tile 128x64, 256 threads, 3 CTAs/SM ----------------
// substage 12KB: Ah@0(4K), Al@4096(4K), Bh@8192(2K), Bl@10240(2K); macro 24KB; bufs @0,24576
// epilogue: hi plane @0 (128 rows x 144B), lo plane @18432
#define G1_SMEM 49152
__global__ void __launch_bounds__(256, 3) gemm1_mma(const float* __restrict__ b1) {
    const int tid = threadIdx.x;
    const int n0 = blockIdx.x * 64;
    const int bx = blockIdx.y;
    const uint32_t smb = smem_u32(smraw);

    // loaders: A 2 chunks/thread (hi+lo same slot), B 1 chunk/thread
    const int ra = tid >> 1, ca = tid & 1;
    const char* gAh = (const char*)(g_ylnh + (size_t)bx * 16384 + ra * 128 + ca * 8);
    const char* gAl = (const char*)(g_ylnl + (size_t)bx * 16384 + ra * 128 + ca * 8);
    const uint32_t dA = (uint32_t)(ra * 32 + ((ca ^ ((ra >> 2) & 1)) * 16));
    const int tb = tid & 127, rb = tb >> 1, cb = tb & 1;
    const char* gB = (const char*)((tid < 128 ? g_w1h : g_w1l) + (size_t)(n0 + rb) * 128 + cb * 8);
    const uint32_t dB = (uint32_t)(8192 + (tid < 128 ? 0 : 2048) + rb * 32 + ((cb ^ ((rb >> 2) & 1)) * 16));

    const int L = tid & 31, wid = tid >> 5, wm = wid & 3, wn = wid >> 2;  // wm 0..3 (m32), wn 0..1 (n32)
    const int ar = wm * 32 + ((L & 7) | (((L >> 3) & 1) << 3));
    const int asw = (((L >> 4) & 1) ^ ((ar >> 2) & 1)) & 1;
    const int br = wn * 32 + ((L & 7) | (((L >> 4) & 1) << 3));
    const int bsw = (((L >> 3) & 1) ^ ((br >> 2) & 1)) & 1;

    float acc[2][4][4];
    #pragma unroll
    for (int i = 0; i < 2; ++i)
        #pragma unroll
        for (int j = 0; j < 4; ++j)
            #pragma unroll
            for (int k = 0; k < 4; ++k) acc[i][j][k] = 0.f;

    auto load_macro = [&](uint32_t bufoff, int ms) {
        #pragma unroll
        for (int s = 0; s < 2; ++s) {
            int ks = 2 * ms + s;
            uint32_t so = bufoff + (uint32_t)s * 12288u;
            CP_ASYNC(smb + so + dA,          gAh + ks * 32);
            CP_ASYNC(smb + so + 4096u + dA,  gAl + ks * 32);
            CP_ASYNC(smb + so + dB,          gB  + ks * 32);
        }
        CP_COMMIT();
    };

    const int NM = 4;
    load_macro(0u, 0);
    for (int ms = 0; ms < NM; ++ms) {
        if (ms + 1 < NM) {
            load_macro((uint32_t)((ms + 1) & 1) * 24576u, ms + 1);
            CP_WAIT1();
        } else CP_WAIT0();
        __syncthreads();
        uint32_t base = smb + (uint32_t)(ms & 1) * 24576u;
        gemm_compute_subN<2, 4096, 8192, 2048>(base,          ar, asw, br, bsw, acc);
        gemm_compute_subN<2, 4096, 8192, 2048>(base + 12288u, ar, asw, br, bsw, acc);
        __syncthreads();
    }

    // epilogue: gelu + split -> staged smem planes (144B rows) -> coalesced stores
    const int bloc = (bx >= PPB) ? 1 : 0;
    uint* smHI = (uint*)smraw;                 // [128 rows][36 uints]
    uint* smLO = (uint*)(smraw + 18432);
    float sqa[4][2];
    #pragma unroll
    for (int j = 0; j < 4; ++j) { sqa[j][0] = 0.f; sqa[j][1] = 0.f; }

    #pragma unroll
    for (int i = 0; i < 2; ++i) {
        const int m = wm * 32 + i * 16 + (L >> 2);
        #pragma unroll
        for (int j = 0; j < 4; ++j) {
            const int nl = wn * 32 + j * 8 + (L & 3) * 2;
            float b10 = __ldg(b1 + n0 + nl), b11 = __ldg(b1 + n0 + nl + 1);
            float v00 = gelu_f(acc[i][j][0] + b10);
            float v01 = gelu_f(acc[i][j][1] + b11);
            float v10 = gelu_f(acc[i][j][2] + b10);
            float v11 = gelu_f(acc[i][j][3] + b11);
            sqa[j][0] += v00 * v00 + v10 * v10;
            sqa[j][1] += v01 * v01 + v11 * v11;
            uint hi0, lo0, hi1, lo1;
            split2(v00, v01, hi0, lo0);
            split2(v10, v11, hi1, lo1);
            smHI[m * 36 + (nl >> 1)]       = hi0;
            smLO[m * 36 + (nl >> 1)]       = lo0;
            smHI[(m + 8) * 36 + (nl >> 1)] = hi1;
            smLO[(m + 8) * 36 + (nl >> 1)] = lo1;
        }
    }
    #pragma unroll
    for (int j = 0; j < 4; ++j) {
        float s0 = sqa[j][0], s1 = sqa[j][1];
        #pragma unroll
        for (int o = 16; o >= 4; o >>= 1) {
            s0 += __shfl_xor_sync(0xffffffffu, s0, o);
            s1 += __shfl_xor_sync(0xffffffffu, s1, o);
        }
        if (L < 4) {
            int n = n0 + wn * 32 + j * 8 + L * 2;
            atomicAdd(&g_gsq[bloc * CH + n], s0);
            atomicAdd(&g_gsq[bloc * CH + n + 1], s1);
        }
    }
    __syncthreads();
    #pragma unroll
    for (int t = 0; t < 8; ++t) {
        int idx = t * 256 + tid;               // 0..2047 uint4s
        int plane = idx >> 10;                 // 1024 uint4 per plane
        int rem = idx & 1023;
        int row = rem >> 3, c4 = rem & 7;      // 8 uint4 per row
        uint4 v = *(const uint4*)(smraw + (uint32_t)plane * 18432u + row * 144 + c4 * 16);
        ushort* base = (plane ? g_hl : g_hh) + (size_t)bx * 65536 + (size_t)row * 512 + n0;
        *(uint4*)((char*)base + c4 * 16) = v;
    }
}

// ---------------- K4: GRN scale + bias2 (parallelized) ----------------
__global__ void grn_prep_kernel(const float* __restrict__ grn_g, const float* __restrict__ grn_b,
                                const float* __restrict__ w2, const float* __restrict__ b2) {
    if (blockIdx.x == 0) {
        __shared__ float red[512];
        int e = threadIdx.x;
        for (int b = 0; b < BATCH; ++b) {
            float g = sqrtf(g_gsq[b * CH + e]);
            red[e] = g;
            __syncthreads();
            for (int o = 256; o > 0; o >>= 1) {
                if (e < o) red[e] += red[e + o];
                __syncthreads();
            }
            float mean = red[0] * (1.f / 512.f);
            __syncthreads();
            float nx = g / (mean + 1e-6f);
            g_s[b * CH + e] = 1.f + grn_g[e] * nx;
        }
    } else {
        __shared__ float part[512];
        int c = threadIdx.x & 127, eq = threadIdx.x >> 7;
        float a = 0.f;
        #pragma unroll 4
        for (int e = eq * 128; e < eq * 128 + 128; ++e)
            a += grn_b[e] * w2[e * C_ + c];
        part[threadIdx.x] = a;
        __syncthreads();
        if (eq == 0)
            g_bias2[c] = b2[c] + part[c] + part[c + 128] + part[c + 256] + part[c + 384];
    }
}

// ---------------- K4b: scaled w2 -> transposed split bf16 planes [b][c][e] ----------------
__global__ void w2cvt_kernel(const float* __restrict__ w2) {
    int id = blockIdx.x * 512 + threadIdx.x;
    int e = id >> 7, c = id & 127;
    float w = w2[id];
    #pragma unroll
    for (int b = 0; b < BATCH; ++b) {
        float v = g_s[b * CH + e] * w;
        __nv_bfloat16 h = __float2bfloat16_rn(v);
        float rem = v - __bfloat162float(h);
        g_w2h[(size_t)b * 65536 + c * 512 + e] = __bfloat16_as_ushort(h);
        g_w2l[(size_t)b * 65536 + c * 512 + e] = __bfloat16_as_ushort(__float2bfloat16_rn(rem));
    }
}

// ---------------- K5: GEMM2 tile 256x128, 512 threads, 2-stage (R13 proven) ----------------
#define G2_SMEM 132096
#define PPB2    432
__global__ void __launch_bounds__(512) gemm2_mma(const float* __restrict__ xin,
                                                 float* __restrict__ out) {
    const int tid = threadIdx.x;
    const int bx = blockIdx.x;
    const int bloc = (bx >= PPB2) ? 1 : 0;
    const uint32_t smb = smem_u32(smraw);

    const int ra = tid >> 1, ca = tid & 1;
    const ushort* gAh = g_hh + (size_t)bx * 131072 + (size_t)ra * 512 + ca * 8;
    const ushort* gAl = g_hl + (size_t)bx * 131072 + (size_t)ra * 512 + ca * 8;
    const uint32_t dAc = (uint32_t)(ra * 32 + ((ca ^ ((ra >> 2) & 1)) * 16));
    const int rb = (tid & 255) >> 1, cb = tid & 1;
    const ushort* gB = (tid < 256 ? g_w2h : g_w2l) + (size_t)bloc * 65536 + (size_t)rb * 512 + cb * 8;
    const uint32_t dBc = (uint32_t)(16384 + (tid < 256 ? 0 : 4096) + rb * 32 + ((cb ^ ((rb >> 2) & 1)) * 16));

    const int L = tid & 31, wid = tid >> 5, wm = wid & 3, wn = wid >> 2;
    const int ar = wm * 64 + ((L & 7) | (((L >> 3) & 1) << 3));
    const int asw = (((L >> 4) & 1) ^ ((ar >> 2) & 1)) & 1;
    const int br = wn * 32 + ((L & 7) | (((L >> 4) & 1) << 3));
    const int bsw = (((L >> 3) & 1) ^ ((br >> 2) & 1)) & 1;

    float acc[4][4][4];
    #pragma unroll
    for (int i = 0; i < 4; ++i)
        #pragma unroll
        for (int j = 0; j < 4; ++j)
            #pragma unroll
            for (int k = 0; k < 4; ++k) acc[i][j][k] = 0.f;

    auto load_macro = [&](uint32_t bufoff, int ms) {
        #pragma unroll
        for (int s = 0; s < 2; ++s) {
            int ks = 2 * ms + s;
            uint32_t so = bufoff + (uint32_t)s * 24576u;
            CP_ASYNC(smb + so + dAc,          (const char*)(gAh + ks * 16));
            CP_ASYNC(smb + so + dAc + 8192u,  (const char*)(gAl + ks * 16));
            CP_ASYNC(smb + so + dBc,          (const char*)(gB  + ks * 16));
        }
        CP_COMMIT();
    };

    const int NM = 16;
    load_macro(0u, 0);
    for (int ms = 0; ms < NM; ++ms) {
        if (ms + 1 < NM) {
            load_macro((uint32_t)((ms + 1) & 1) * 49152u, ms + 1);
            CP_WAIT1();
        } else CP_WAIT0();
        __syncthreads();
        uint32_t base = smb + (uint32_t)(ms & 1) * 49152u;
        gemm_compute_subN<4, 8192, 16384, 4096>(base,          ar, asw, br, bsw, acc);
        gemm_compute_subN<4, 8192, 16384, 4096>(base + 24576u, ar, asw, br, bsw, acc);
        __syncthreads();
    }

    float* Cs = (float*)smraw;
    #pragma unroll
    for (int i = 0; i < 4; ++i) {
        const int m = wm * 64 + i * 16 + (L >> 2);
        #pragma unroll
        for (int j = 0; j < 4; ++j) {
            const int c = wn * 32 + j * 8 + (L & 3) * 2;
            float bv0 = g_bias2[c], bv1 = g_bias2[c + 1];
            Cs[m * 129 + c]           = acc[i][j][0] + bv0;
            Cs[m * 129 + c + 1]       = acc[i][j][1] + bv1;
            Cs[(m + 8) * 129 + c]     = acc[i][j][2] + bv0;
            Cs[(m + 8) * 129 + c + 1] = acc[i][j][3] + bv1;
        }
    }
    __syncthreads();
    const int p0 = (bx - bloc * PPB2) * 256;
    #pragma unroll
    for (int t = 0; t < 64; ++t) {
        int idx = tid + 512 * t;
        int p = idx & 255, c = idx >> 8;
        size_t gi = ((size_t)(bloc * C_ + c)) * S_ + p0 + p;
        out[gi] = xin[gi] + Cs[p * 129 + c];
    }
}

// ---------------- launch ----------------
extern "C" void kernel_launch(void* const* d_in, const int* in_sizes, int n_in,
                              void* d_out, int out_size) {
    (void)in_sizes; (void)n_in; (void)out_size;
    const float* x     = (const float*)d_in[0];
    const float* dw_w  = (const float*)d_in[1];
    const float* dw_b  = (const float*)d_in[2];
    const float* ln_g  = (const float*)d_in[3];
    const float* ln_b  = (const float*)d_in[4];
    const float* w1    = (const float*)d_in[5];
    const float* b1    = (const float*)d_in[6];
    const float* grn_g = (const float*)d_in[7];
    const float* grn_b = (const float*)d_in[8];
    const float* w2    = (const float*)d_in[9];
    const float* b2    = (const float*)d_in[10];
    float* out = (float*)d_out;

    const int conv_smem = (7 * 2916 + 343 + 2304) * 4;   // 92236
    cudaFuncSetAttribute(conv_dw_kernel, cudaFuncAttributeMaxDynamicSharedMemorySize, conv_smem);
    cudaFuncSetAttribute(gemm1_mma, cudaFuncAttributeMaxDynamicSharedMemorySize, G1_SMEM);
    cudaFuncSetAttribute(gemm2_mma, cudaFuncAttributeMaxDynamicSharedMemorySize, G2_SMEM);

    w1cvt_zero_kernel<<<129, 512>>>(w1);
    conv_dw_kernel<<<dim3(4, C_, BATCH), 192, conv_smem>>>(x, dw_w);
    trans_ln_kernel<<<dim3(S_ / 32, BATCH), 256>>>(dw_b, ln_g, ln_b);
    gemm1_mma<<<dim3(8, NPANEL), 256, G1_SMEM>>>(b1);
    grn_prep_kernel<<<2, 512>>>(grn_g, grn_b, w2, b2);
    w2cvt_kernel<<<128, 512>>>(w2);
    gemm2_mma<<<NPANEL / 2, 512, G2_SMEM>>>(x, out);
}

// round 16
// speedup vs baseline: 1.0288x; 1.0177x over previous
#include <cuda_runtime.h>
#include <cuda_bf16.h>
#include <math.h>
#include <stdint.h>

#define C_     128
#define BATCH  2
#define S_     110592          // 48*48*48
#define NPTS   221184
#define CH     512
#define NPANEL 1728            // NPTS/128
#define PPB    864             // panels per batch

typedef unsigned int uint;
typedef unsigned short ushort;

extern __shared__ __align__(128) unsigned char smraw[];

// ---------------- scratch ----------------
__device__ float  g_yconv[(size_t)BATCH * C_ * S_];
__device__ ushort g_ylnh[(size_t)NPTS * C_];            // LN out hi bf16, [panel][m][k]
__device__ ushort g_ylnl[(size_t)NPTS * C_];
__device__ ushort g_hh  [(size_t)NPTS * CH];            // gelu out hi, [panel][m][e]
__device__ ushort g_hl  [(size_t)NPTS * CH];
__device__ ushort g_w1h [CH * C_];                      // w1^T hi: [e][c]
__device__ ushort g_w1l [CH * C_];
__device__ ushort g_w2h [BATCH * C_ * CH];              // scaled w2^T hi: [b][c][e]
__device__ ushort g_w2l [BATCH * C_ * CH];
__device__ float  g_gsq [BATCH * CH];
__device__ float  g_s   [BATCH * CH];
__device__ float  g_bias2[C_];

// ---------------- PTX helpers ----------------
__device__ __forceinline__ uint32_t smem_u32(const void* p) {
    uint32_t a;
    asm("{ .reg .u64 t; cvta.to.shared.u64 t, %1; cvt.u32.u64 %0, t; }" : "=r"(a) : "l"(p));
    return a;
}
#define CP_ASYNC(dst, src)    asm volatile("cp.async.cg.shared.global [%0], [%1], 16;" :: "r"(dst), "l"(src))
#define CP_ASYNC_CA(dst, src) asm volatile("cp.async.ca.shared.global [%0], [%1], 16;" :: "r"(dst), "l"(src))
#define CP_COMMIT()        asm volatile("cp.async.commit_group;")
#define CP_WAIT1()         asm volatile("cp.async.wait_group 1;")
#define CP_WAIT0()         asm volatile("cp.async.wait_group 0;")

__device__ __forceinline__ void ldsm4(uint* r, uint32_t addr) {
    asm volatile("ldmatrix.sync.aligned.m8n8.x4.shared.b16 {%0,%1,%2,%3}, [%4];"
        : "=r"(r[0]), "=r"(r[1]), "=r"(r[2]), "=r"(r[3]) : "r"(addr));
}
__device__ __forceinline__ void mma_bf16(float* c, const uint* a, uint b0, uint b1) {
    asm volatile("mma.sync.aligned.m16n8k16.row.col.f32.bf16.bf16.f32 "
        "{%0,%1,%2,%3}, {%4,%5,%6,%7}, {%8,%9}, {%0,%1,%2,%3};"
        : "+f"(c[0]), "+f"(c[1]), "+f"(c[2]), "+f"(c[3])
        : "r"(a[0]), "r"(a[1]), "r"(a[2]), "r"(a[3]), "r"(b0), "r"(b1));
}
__device__ __forceinline__ void split2(float a, float b, uint& hi, uint& lo) {
    __nv_bfloat16 ah = __float2bfloat16_rn(a), bh = __float2bfloat16_rn(b);
    float ar = a - __bfloat162float(ah), br = b - __bfloat162float(bh);
    __nv_bfloat16 al = __float2bfloat16_rn(ar), bl = __float2bfloat16_rn(br);
    hi = ((uint)__bfloat16_as_ushort(bh) << 16) | (uint)__bfloat16_as_ushort(ah);
    lo = ((uint)__bfloat16_as_ushort(bl) << 16) | (uint)__bfloat16_as_ushort(al);
}
__device__ __forceinline__ float gelu_f(float v) {
    return 0.5f * v * (1.0f + erff(v * 0.70710678118654752f));
}

// generic 16-k sub-stage compute; NI = number of 16-row A tiles per warp.
template<int NI, int ALO, int BBASE, int BLO>
__device__ __forceinline__ void gemm_compute_subN(uint32_t sa,
    int ar, int asw, int br, int bsw, float acc[][4][4]) {
    uint aH[NI][4], aL[NI][4], bH[2][4], bL[2][4];
    uint32_t abase = sa + (uint32_t)(ar * 32 + asw * 16);
    #pragma unroll
    for (int i = 0; i < NI; ++i) ldsm4(aH[i], abase + i * 512u);
    #pragma unroll
    for (int i = 0; i < NI; ++i) ldsm4(aL[i], abase + (uint32_t)ALO + i * 512u);
    uint32_t bbase = sa + (uint32_t)BBASE + (uint32_t)(br * 32 + bsw * 16);
    #pragma unroll
    for (int j = 0; j < 2; ++j) ldsm4(bH[j], bbase + j * 512u);
    #pragma unroll
    for (int j = 0; j < 2; ++j) ldsm4(bL[j], bbase + (uint32_t)BLO + j * 512u);
    #pragma unroll
    for (int i = 0; i < NI; ++i)
        #pragma unroll
        for (int j = 0; j < 4; ++j) {
            uint h0 = bH[j >> 1][(j & 1) * 2], h1 = bH[j >> 1][(j & 1) * 2 + 1];
            uint l0 = bL[j >> 1][(j & 1) * 2], l1 = bL[j >> 1][(j & 1) * 2 + 1];
            mma_bf16(acc[i][j], aH[i], h0, h1);
            mma_bf16(acc[i][j], aH[i], l0, l1);
            mma_bf16(acc[i][j], aL[i], h0, h1);
        }
}

// ---------------- K0: w1 cvt + zero gsq ----------------
__global__ void w1cvt_zero_kernel(const float* __restrict__ w1) {
    if (blockIdx.x == 128) {
        int i = threadIdx.x;
        if (i < BATCH * CH) g_gsq[i] = 0.f;
        return;
    }
    int id = blockIdx.x * 512 + threadIdx.x;
    int cc = id >> 9, e = id & 511;
    float v = w1[id];
    __nv_bfloat16 h = __float2bfloat16_rn(v);
    float rem = v - __bfloat162float(h);
    g_w1h[e * 128 + cc] = __bfloat16_as_ushort(h);
    g_w1l[e * 128 + cc] = __bfloat16_as_ushort(__float2bfloat16_rn(rem));
}

// ---------------- K1: depthwise 7x7x7 conv (plain FFMA, known-best) ----------------
__global__ void conv_dw_kernel(const float* __restrict__ x, const float* __restrict__ dw_w) {
    float* sm = (float*)smraw;
    float* planes = sm;
    float* wsm    = sm + 7 * 2916;
    float* outsm  = wsm + 343;

    const int tid = threadIdx.x;
    const int dstart = blockIdx.x * 12;
    const int c = blockIdx.y;
    const int b = blockIdx.z;
    const size_t xbase = ((size_t)(b * C_ + c)) * S_;

    for (int i = tid; i < 343; i += 192) wsm[i] = dw_w[c * 343 + i];

    for (int pl = 0; pl < 7; ++pl) {
        int din = dstart - 3 + pl;
        int slot = ((din % 7) + 7) % 7;
        float* dst = planes + slot * 2916;
        if (din < 0 || din >= 48) {
            for (int i = tid; i < 2916; i += 192) dst[i] = 0.f;
        } else {
            const float* src = x + xbase + (size_t)din * 2304;
            for (int i = tid; i < 2916; i += 192) {
                int hh = i / 54 - 3, ww = i % 54 - 3;
                dst[i] = (hh >= 0 && hh < 48 && ww >= 0 && ww < 48) ? src[hh * 48 + ww] : 0.f;
            }
        }
    }

    const int tx = tid & 7, ty = tid >> 3;
    const int w0 = tx * 6, h0 = ty * 2;

    for (int d = dstart; d < dstart + 12; ++d) {
        __syncthreads();
        float acc[2][6];
        #pragma unroll
        for (int r = 0; r < 2; ++r)
            #pragma unroll
            for (int j = 0; j < 6; ++j) acc[r][j] = 0.f;

        #pragma unroll 1
        for (int dd = 0; dd < 7; ++dd) {
            const float* pl = planes + (((d - 3 + dd) % 7 + 7) % 7) * 2916;
            #pragma unroll
            for (int dh = 0; dh < 7; ++dh) {
                float wv[7];
                #pragma unroll
                for (int k = 0; k < 7; ++k) wv[k] = wsm[dd * 49 + dh * 7 + k];
                #pragma unroll
                for (int r = 0; r < 2; ++r) {
                    const float* row = pl + (h0 + r + dh) * 54 + w0;
                    float xr[12];
                    #pragma unroll
                    for (int q = 0; q < 12; ++q) xr[q] = row[q];
                    #pragma unroll
                    for (int j = 0; j < 6; ++j)
                        #pragma unroll
                        for (int k = 0; k < 7; ++k)
                            acc[r][j] = fmaf(xr[j + k], wv[k], acc[r][j]);
                }
            }
        }
        #pragma unroll
        for (int r = 0; r < 2; ++r)
            #pragma unroll
            for (int j = 0; j < 6; ++j)
                outsm[(h0 + r) * 48 + w0 + j] = acc[r][j];
        __syncthreads();
        float* dst = g_yconv + xbase + (size_t)d * 2304;
        for (int i = tid; i < 2304; i += 192) dst[i] = outsm[i];
        if (d + 1 < dstart + 12) {
            int din = d + 4;
            int slot = ((din % 7) + 7) % 7;
            float* dstp = planes + slot * 2916;
            if (din >= 48) {
                for (int i = tid; i < 2916; i += 192) dstp[i] = 0.f;
            } else {
                const float* src = x + xbase + (size_t)din * 2304;
                for (int i = tid; i < 2916; i += 192) {
                    int hh = i / 54 - 3, ww = i % 54 - 3;
                    dstp[i] = (hh >= 0 && hh < 48 && ww >= 0 && ww < 48) ? src[hh * 48 + ww] : 0.f;
                }
            }
        }
    }
}

// ---------------- K2: transpose + dw_b + LN -> split bf16 [panel][m][k] ----------------
__global__ void trans_ln_kernel(const float* __restrict__ dwb,
                                const float* __restrict__ lng,
                                const float* __restrict__ lnb) {
    __shared__ float tile[C_ * 33];
    __shared__ float ps[256], pq[256], musm[32], rssm[32];
    const int tid = threadIdx.x;
    const int tx = tid & 31, ty = tid >> 5;
    const int p0 = blockIdx.x * 32;
    const int b = blockIdx.y;

    for (int g = 0; g < 16; ++g) {
        int c = ty * 16 + g;
        tile[c * 33 + tx] = g_yconv[((size_t)(b * C_ + c)) * S_ + p0 + tx] + dwb[c];
    }
    __syncthreads();
    float s = 0.f, q = 0.f;
    for (int g = 0; g < 16; ++g) {
        float v = tile[(ty * 16 + g) * 33 + tx];
        s += v; q += v * v;
    }
    ps[ty * 32 + tx] = s; pq[ty * 32 + tx] = q;
    __syncthreads();
    if (ty == 0) {
        float S1 = 0.f, Q1 = 0.f;
        for (int u = 0; u < 8; ++u) { S1 += ps[u * 32 + tx]; Q1 += pq[u * 32 + tx]; }
        float mu = S1 * (1.f / 128.f);
        float var = Q1 * (1.f / 128.f) - mu * mu;
        musm[tx] = mu;
        rssm[tx] = rsqrtf(var + 1e-6f);
    }
    __syncthreads();
    size_t panel = ((size_t)b * S_ + p0) >> 7;
    int mo = (int)(((size_t)b * S_ + p0) & 127);
    ushort* dh = g_ylnh + panel * 16384;
    ushort* dl = g_ylnl + panel * 16384;
    for (int t = 0; t < 16; ++t) {
        int idx = tid + 256 * t;
        int c = idx & 127, pp = idx >> 7;
        float v = (tile[c * 33 + pp] - musm[pp]) * rssm[pp] * lng[c] + lnb[c];
        __nv_bfloat16 h = __float2bfloat16_rn(v);
        float rem = v - __bfloat162float(h);
        dh[(mo + pp) * 128 + c] = __bfloat16_as_ushort(h);
        dl[(mo + pp) * 128 + c] = __bfloat16_as_ushort(__float2bfloat16_rn(rem));
    }
}

// ---------------- K3: GEMM1 tile 128x128, 256 threads, staged epilogue (R13 best) ----------------
// mainloop 64KB; epilogue: hi plane @0 (128 rows x 272B), lo plane @34816
#define G1_SMEM 69632
__global__ void __launch_bounds__(256) gemm1_mma(const float* __restrict__ b1) {
    const int tid = threadIdx.x;
    const int n0 = blockIdx.x * 128;
    const int bx = blockIdx.y;
    const uint32_t smb = smem_u32(smraw);

    const int r = tid >> 1, cc = tid & 1;
    const int csw = (cc ^ ((r >> 2) & 1)) & 1;
    const uint32_t sdst0 = smb + (uint32_t)(r * 32 + csw * 16);
    const char* gAh = (const char*)(g_ylnh + (size_t)bx * 16384 + r * 128 + cc * 8);
    const char* gAl = (const char*)(g_ylnl + (size_t)bx * 16384 + r * 128 + cc * 8);
    const char* gBh = (const char*)(g_w1h + (size_t)(n0 + r) * 128 + cc * 8);
    const char* gBl = (const char*)(g_w1l + (size_t)(n0 + r) * 128 + cc * 8);

    const int L = tid & 31, wid = tid >> 5, wm = wid & 1, wn = wid >> 1;
    const int ar = wm * 64 + ((L & 7) | (((L >> 3) & 1) << 3));
    const int asw = (((L >> 4) & 1) ^ ((ar >> 2) & 1)) & 1;
    const int br = wn * 32 + ((L & 7) | (((L >> 4) & 1) << 3));
    const int bsw = (((L >> 3) & 1) ^ ((br >> 2) & 1)) & 1;

    float acc[4][4][4];
    #pragma unroll
    for (int i = 0; i < 4; ++i)
        #pragma unroll
        for (int j = 0; j < 4; ++j)
            #pragma unroll
            for (int k = 0; k < 4; ++k) acc[i][j][k] = 0.f;

    auto load_macro = [&](uint32_t bufoff, int ms) {
        #pragma unroll
        for (int s = 0; s < 2; ++s) {
            int ks = 2 * ms + s;
            uint32_t so = bufoff + (uint32_t)s * 16384u;
            CP_ASYNC(sdst0 + so,              gAh + ks * 32);
            CP_ASYNC(sdst0 + so + 4096u,      gAl + ks * 32);
            CP_ASYNC_CA(sdst0 + so + 8192u,   gBh + ks * 32);
            CP_ASYNC_CA(sdst0 + so + 12288u,  gBl + ks * 32);
        }
        CP_COMMIT();
    };

    const int NM = 4;
    load_macro(0u, 0);
    for (int ms = 0; ms < NM; ++ms) {
        if (ms + 1 < NM) {
            load_macro((uint32_t)((ms + 1) & 1) * 32768u, ms + 1);
            CP_WAIT1();
        } else CP_WAIT0();
        __syncthreads();
        uint32_t base = smb + (uint32_t)(ms & 1) * 32768u;
        gemm_compute_subN<4, 4096, 8192, 4096>(base,          ar, asw, br, bsw, acc);
        gemm_compute_subN<4, 4096, 8192, 4096>(base + 16384u, ar, asw, br, bsw, acc);
        __syncthreads();
    }

    // epilogue: gelu + split -> staged smem planes (272B rows, 16B-aligned) -> coalesced stores
    const int bloc = (bx >= PPB) ? 1 : 0;
    uint* smHI = (uint*)smraw;                 // [128 rows][68 uints]
    uint* smLO = (uint*)(smraw + 34816);
    float sqa[4][2];
    #pragma unroll
    for (int j = 0; j < 4; ++j) { sqa[j][0] = 0.f; sqa[j][1] = 0.f; }

    #pragma unroll
    for (int i = 0; i < 4; ++i) {
        const int m = wm * 64 + i * 16 + (L >> 2);
        #pragma unroll
        for (int j = 0; j < 4; ++j) {
            const int nl = wn * 32 + j * 8 + (L & 3) * 2;
            float b10 = __ldg(b1 + n0 + nl), b11 = __ldg(b1 + n0 + nl + 1);
            float v00 = gelu_f(acc[i][j][0] + b10);
            float v01 = gelu_f(acc[i][j][1] + b11);
            float v10 = gelu_f(acc[i][j][2] + b10);
            float v11 = gelu_f(acc[i][j][3] + b11);
            sqa[j][0] += v00 * v00 + v10 * v10;
            sqa[j][1] += v01 * v01 + v11 * v11;
            uint hi0, lo0, hi1, lo1;
            split2(v00, v01, hi0, lo0);
            split2(v10, v11, hi1, lo1);
            smHI[m * 68 + (nl >> 1)]       = hi0;
            smLO[m * 68 + (nl >> 1)]       = lo0;
            smHI[(m + 8) * 68 + (nl >> 1)] = hi1;
            smLO[(m + 8) * 68 + (nl >> 1)] = lo1;
        }
    }
    #pragma unroll
    for (int j = 0; j < 4; ++j) {
        float s0 = sqa[j][0], s1 = sqa[j][1];
        #pragma unroll
        for (int o = 16; o >= 4; o >>= 1) {
            s0 += __shfl_xor_sync(0xffffffffu, s0, o);
            s1 += __shfl_xor_sync(0xffffffffu, s1, o);
        }
        if (L < 4) {
            int n = n0 + wn * 32 + j * 8 + L * 2;
            atomicAdd(&g_gsq[bloc * CH + n], s0);
            atomicAdd(&g_gsq[bloc * CH + n + 1], s1);
        }
    }
    __syncthreads();
    #pragma unroll
    for (int t = 0; t < 16; ++t) {
        int idx = t * 256 + tid;               // 0..4095 uint4s
        int plane = idx >> 11;                 // 2048 uint4 per plane
        int rem = idx & 2047;
        int row = rem >> 4, c4 = rem & 15;     // 16 uint4 per row
        uint4 v = *(const uint4*)(smraw + (uint32_t)plane * 34816u + row * 272 + c4 * 16);
        ushort* base = (plane ? g_hl : g_hh) + (size_t)bx * 65536 + (size_t)row * 512 + n0;
        *(uint4*)((char*)base + c4 * 16) = v;
    }
}

// ---------------- K4: GRN scale + bias2 (parallelized) ----------------
__global__ void grn_prep_kernel(const float* __restrict__ grn_g, const float* __restrict__ grn_b,
                                const float* __restrict__ w2, const float* __restrict__ b2) {
    if (blockIdx.x == 0) {
        __shared__ float red[512];
        int e = threadIdx.x;
        for (int b = 0; b < BATCH; ++b) {
            float g = sqrtf(g_gsq[b * CH + e]);
            red[e] = g;
            __syncthreads();
            for (int o = 256; o > 0; o >>= 1) {
                if (e < o) red[e] += red[e + o];
                __syncthreads();
            }
            float mean = red[0] * (1.f / 512.f);
            __syncthreads();
            float nx = g / (mean + 1e-6f);
            g_s[b * CH + e] = 1.f + grn_g[e] * nx;
        }
    } else {
        __shared__ float part[512];
        int c = threadIdx.x & 127, eq = threadIdx.x >> 7;
        float a = 0.f;
        #pragma unroll 4
        for (int e = eq * 128; e < eq * 128 + 128; ++e)
            a += grn_b[e] * w2[e * C_ + c];
        part[threadIdx.x] = a;
        __syncthreads();
        if (eq == 0)
            g_bias2[c] = b2[c] + part[c] + part[c + 128] + part[c + 256] + part[c + 384];
    }
}

// ---------------- K4b: scaled w2 -> transposed split bf16 planes [b][c][e] ----------------
__global__ void w2cvt_kernel(const float* __restrict__ w2) {
    int id = blockIdx.x * 512 + threadIdx.x;
    int e = id >> 7, c = id & 127;
    float w = w2[id];
    #pragma unroll
    for (int b = 0; b < BATCH; ++b) {
        float v = g_s[b * CH + e] * w;
        __nv_bfloat16 h = __float2bfloat16_rn(v);
        float rem = v - __bfloat162float(h);
        g_w2h[(size_t)b * 65536 + c * 512 + e] = __bfloat16_as_ushort(h);
        g_w2l[(size_t)b * 65536 + c * 512 + e] = __bfloat16_as_ushort(__float2bfloat16_rn(rem));
    }
}

// ---------------- K5: GEMM2 tile 256x128, 512 threads, 2-stage (R13 proven) ----------------
#define G2_SMEM 132096
#define PPB2    432
__global__ void __launch_bounds__(512) gemm2_mma(const float* __restrict__ xin,
                                                 float* __restrict__ out) {
    const int tid = threadIdx.x;
    const int bx = blockIdx.x;
    const int bloc = (bx >= PPB2) ? 1 : 0;
    const uint32_t smb = smem_u32(smraw);

    const int ra = tid >> 1, ca = tid & 1;
    const ushort* gAh = g_hh + (size_t)bx * 131072 + (size_t)ra * 512 + ca * 8;
    const ushort* gAl = g_hl + (size_t)bx * 131072 + (size_t)ra * 512 + ca * 8;
    const uint32_t dAc = (uint32_t)(ra * 32 + ((ca ^ ((ra >> 2) & 1)) * 16));
    const int rb = (tid & 255) >> 1, cb = tid & 1;
    const ushort* gB = (tid < 256 ? g_w2h : g_w2l) + (size_t)bloc * 65536 + (size_t)rb * 512 + cb * 8;
    const uint32_t dBc = (uint32_t)(16384 + (tid < 256 ? 0 : 4096) + rb * 32 + ((cb ^ ((rb >> 2) & 1)) * 16));

    const int L = tid & 31, wid = tid >> 5, wm = wid & 3, wn = wid >> 2;
    const int ar = wm * 64 + ((L & 7) | (((L >> 3) & 1) << 3));
    const int asw = (((L >> 4) & 1) ^ ((ar >> 2) & 1)) & 1;
    const int br = wn * 32 + ((L & 7) | (((L >> 4) & 1) << 3));
    const int bsw = (((L >> 3) & 1) ^ ((br >> 2) & 1)) & 1;

    float acc[4][4][4];
    #pragma unroll
    for (int i = 0; i < 4; ++i)
        #pragma unroll
        for (int j = 0; j < 4; ++j)
            #pragma unroll
            for (int k = 0; k < 4; ++k) acc[i][j][k] = 0.f;

    auto load_macro = [&](uint32_t bufoff, int ms) {
        #pragma unroll
        for (int s = 0; s < 2; ++s) {
            int ks = 2 * ms + s;
            uint32_t so = bufoff + (uint32_t)s * 24576u;
            CP_ASYNC(smb + so + dAc,             (const char*)(gAh + ks * 16));
            CP_ASYNC(smb + so + dAc + 8192u,     (const char*)(gAl + ks * 16));
            CP_ASYNC_CA(smb + so + dBc,          (const char*)(gB  + ks * 16));
        }
        CP_COMMIT();
    };

    const int NM = 16;
    load_macro(0u, 0);
    for (int ms = 0; ms < NM; ++ms) {
        if (ms + 1 < NM) {
            load_macro((uint32_t)((ms + 1) & 1) * 49152u, ms + 1);
            CP_WAIT1();
        } else CP_WAIT0();
        __syncthreads();
        uint32_t base = smb + (uint32_t)(ms & 1) * 49152u;
        gemm_compute_subN<4, 8192, 16384, 4096>(base,          ar, asw, br, bsw, acc);
        gemm_compute_subN<4, 8192, 16384, 4096>(base + 24576u, ar, asw, br, bsw, acc);
        __syncthreads();
    }

    float* Cs = (float*)smraw;
    #pragma unroll
    for (int i = 0; i < 4; ++i) {
        const int m = wm * 64 + i * 16 + (L >> 2);
        #pragma unroll
        for (int j = 0; j < 4; ++j) {
            const int c = wn * 32 + j * 8 + (L & 3) * 2;
            float bv0 = g_bias2[c], bv1 = g_bias2[c + 1];
            Cs[m * 129 + c]           = acc[i][j][0] + bv0;
            Cs[m * 129 + c + 1]       = acc[i][j][1] + bv1;
            Cs[(m + 8) * 129 + c]     = acc[i][j][2] + bv0;
            Cs[(m + 8) * 129 + c + 1] = acc[i][j][3] + bv1;
        }
    }
    __syncthreads();
    const int p0 = (bx - bloc * PPB2) * 256;
    #pragma unroll
    for (int t = 0; t < 64; ++t) {
        int idx = tid + 512 * t;
        int p = idx & 255, c = idx >> 8;
        size_t gi = ((size_t)(bloc * C_ + c)) * S_ + p0 + p;
        out[gi] = xin[gi] + Cs[p * 129 + c];
    }
}

// ---------------- launch ----------------
extern "C" void kernel_launch(void* const* d_in, const int* in_sizes, int n_in,
                              void* d_out, int out_size) {
    (void)in_sizes; (void)n_in; (void)out_size;
    const float* x     = (const float*)d_in[0];
    const float* dw_w  = (const float*)d_in[1];
    const float* dw_b  = (const float*)d_in[2];
    const float* ln_g  = (const float*)d_in[3];
    const float* ln_b  = (const float*)d_in[4];
    const float* w1    = (const float*)d_in[5];
    const float* b1    = (const float*)d_in[6];
    const float* grn_g = (const float*)d_in[7];
    const float* grn_b = (const float*)d_in[8];
    const float* w2    = (const float*)d_in[9];
    const float* b2    = (const float*)d_in[10];
    float* out = (float*)d_out;

    const int conv_smem = (7 * 2916 + 343 + 2304) * 4;   // 92236
    cudaFuncSetAttribute(conv_dw_kernel, cudaFuncAttributeMaxDynamicSharedMemorySize, conv_smem);
    cudaFuncSetAttribute(gemm1_mma, cudaFuncAttributeMaxDynamicSharedMemorySize, G1_SMEM);
    cudaFuncSetAttribute(gemm2_mma, cudaFuncAttributeMaxDynamicSharedMemorySize, G2_SMEM);

    w1cvt_zero_kernel<<<129, 512>>>(w1);
    conv_dw_kernel<<<dim3(4, C_, BATCH), 192, conv_smem>>>(x, dw_w);
    trans_ln_kernel<<<dim3(S_ / 32, BATCH), 256>>>(dw_b, ln_g, ln_b);
    gemm1_mma<<<dim3(4, NPANEL), 256, G1_SMEM>>>(b1);
    grn_prep_kernel<<<2, 512>>>(grn_g, grn_b, w2, b2);
    w2cvt_kernel<<<128, 512>>>(w2);
    gemm2_mma<<<NPANEL / 2, 512, G2_SMEM>>>(x, out);
}